// round 5
// baseline (speedup 1.0000x reference)
#include <cuda_runtime.h>
#include <math.h>

// Problem constants
#define BB 2
#define TT 1024
#define CC 1024
#define HH 16
#define LL 12
#define VV 50257
#define HD 64
#define MM (BB*TT)      // 2048 rows in the token stream
#define FF (4*CC)       // 4096 MLP hidden

// ---------------------------------------------------------------------------
// Scratch (static device arrays -- no allocation allowed)
// ---------------------------------------------------------------------------
__device__ float g_x  [MM*CC];   // residual stream
__device__ float g_h  [MM*CC];   // LN output
__device__ float g_q  [MM*CC];
__device__ float g_k  [MM*CC];
__device__ float g_v  [MM*CC];
__device__ float g_att[MM*CC];   // attention output y
__device__ float g_ffn[MM*FF];   // MLP hidden (post-GELU)
__device__ float g_nll[MM];      // per-row NLL

// ---------------------------------------------------------------------------
// Embedding: x[b,t,:] = tok_emb[idx[b,t],:] + pos_emb[t,:]
// ---------------------------------------------------------------------------
__global__ void embed_kernel(const int* __restrict__ idx,
                             const float* __restrict__ tok,
                             const float* __restrict__ pos,
                             float* __restrict__ x)
{
    int row = blockIdx.x;               // 0..MM-1
    int t   = row % TT;
    int id  = idx[row];
    const float* tr = tok + (size_t)id * CC;
    const float* pr = pos + (size_t)t  * CC;
    float* xr = x + (size_t)row * CC;
    for (int c = threadIdx.x; c < CC; c += blockDim.x)
        xr[c] = tr[c] + pr[c];
}

// ---------------------------------------------------------------------------
// LayerNorm (eps=1e-5, population variance) -- one block per row
// ---------------------------------------------------------------------------
__global__ void ln_kernel(const float* __restrict__ x,
                          const float* __restrict__ w,
                          const float* __restrict__ b,
                          float* __restrict__ o)
{
    int row = blockIdx.x;
    const float* xr = x + (size_t)row * CC;
    int tid = threadIdx.x;
    float s = 0.f, ss = 0.f;
    for (int c = tid; c < CC; c += 256) { float v = xr[c]; s += v; ss += v * v; }
    for (int off = 16; off; off >>= 1) {
        s  += __shfl_xor_sync(0xffffffffu, s,  off);
        ss += __shfl_xor_sync(0xffffffffu, ss, off);
    }
    __shared__ float shs[8], shss[8];
    __shared__ float s_mu, s_rstd;
    if ((tid & 31) == 0) { shs[tid >> 5] = s; shss[tid >> 5] = ss; }
    __syncthreads();
    if (tid == 0) {
        float t1 = 0.f, t2 = 0.f;
        for (int i = 0; i < 8; i++) { t1 += shs[i]; t2 += shss[i]; }
        float mu  = t1 / (float)CC;
        float var = t2 / (float)CC - mu * mu;
        s_mu = mu;
        s_rstd = rsqrtf(var + 1e-5f);
    }
    __syncthreads();
    float mu = s_mu, rstd = s_rstd;
    float* orow = o + (size_t)row * CC;
    for (int c = tid; c < CC; c += 256)
        orow[c] = (xr[c] - mu) * rstd * w[c] + b[c];
}

// ---------------------------------------------------------------------------
// SGEMM: out[M,N] = A[M,K] @ B[K,N]  (+ bias[N]) (-> GELU) (+ res[M,N])
// 128x128 block tile, 8-deep K tiles, 8x8 per-thread microtile, 256 threads.
// M is always a multiple of 128 and K a multiple of 8; N may be ragged (head).
// ---------------------------------------------------------------------------
template<bool BIAS, bool RES, bool GELU>
__global__ __launch_bounds__(256)
void gemm_kernel(const float* __restrict__ A, const float* __restrict__ B,
                 const float* __restrict__ bias, const float* __restrict__ res,
                 float* __restrict__ out, int M, int N, int K)
{
    __shared__ float As[8][128];
    __shared__ float Bs[8][132];           // +4 pad (keeps float4 alignment: 132*4%16==0)

    int tid = threadIdx.x;
    int n0 = blockIdx.x * 128;
    int m0 = blockIdx.y * 128;
    int tx = tid & 15;
    int ty = tid >> 4;

    float acc[8][8];
    #pragma unroll
    for (int i = 0; i < 8; i++)
        #pragma unroll
        for (int j = 0; j < 8; j++) acc[i][j] = 0.f;

    int arow = tid >> 1;                   // 0..127
    int acol = (tid & 1) << 2;             // 0 or 4
    int brow = tid >> 5;                   // 0..7
    int bcol = (tid & 31) << 2;            // 0..124

    const float* Aptr = A + (size_t)(m0 + arow) * K + acol;
    const float* Bptr = B + (size_t)brow * N + n0 + bcol;

    for (int kt = 0; kt < K; kt += 8) {
        float4 av = *(const float4*)(Aptr + kt);
        As[acol + 0][arow] = av.x;
        As[acol + 1][arow] = av.y;
        As[acol + 2][arow] = av.z;
        As[acol + 3][arow] = av.w;

        const float* bp = Bptr + (size_t)kt * N;
        int nb = n0 + bcol;
        Bs[brow][bcol + 0] = (nb + 0 < N) ? bp[0] : 0.f;
        Bs[brow][bcol + 1] = (nb + 1 < N) ? bp[1] : 0.f;
        Bs[brow][bcol + 2] = (nb + 2 < N) ? bp[2] : 0.f;
        Bs[brow][bcol + 3] = (nb + 3 < N) ? bp[3] : 0.f;
        __syncthreads();

        #pragma unroll
        for (int kk = 0; kk < 8; kk++) {
            float ra[8], rb[8];
            *(float4*)&ra[0] = *(const float4*)&As[kk][ty * 8];
            *(float4*)&ra[4] = *(const float4*)&As[kk][ty * 8 + 4];
            *(float4*)&rb[0] = *(const float4*)&Bs[kk][tx * 8];
            *(float4*)&rb[4] = *(const float4*)&Bs[kk][tx * 8 + 4];
            #pragma unroll
            for (int i = 0; i < 8; i++)
                #pragma unroll
                for (int j = 0; j < 8; j++)
                    acc[i][j] = fmaf(ra[i], rb[j], acc[i][j]);
        }
        __syncthreads();
    }

    #pragma unroll
    for (int i = 0; i < 8; i++) {
        int row = m0 + ty * 8 + i;
        size_t rbase = (size_t)row * N;
        #pragma unroll
        for (int j = 0; j < 8; j++) {
            int col = n0 + tx * 8 + j;
            if (col < N) {
                float v = acc[i][j];
                if (BIAS) v += bias[col];
                if (GELU) v = 0.5f * v * (1.0f + erff(v * 0.70710678118654752f));
                if (RES)  v += res[rbase + col];
                out[rbase + col] = v;
            }
        }
    }
}

// ---------------------------------------------------------------------------
// Causal flash attention (fp32, online softmax).
// Grid: (T/16, H, B). Block: 256 threads.
// 16 queries x 64-key chunks; thread (r = tid/16, c = tid%16):
//   score phase: 4 keys j = c + 16*jj of row r
//   accum phase: 4 dims  d = c*4 .. c*4+3 of row r
// ---------------------------------------------------------------------------
__global__ __launch_bounds__(256)
void attn_kernel(const float* __restrict__ q, const float* __restrict__ k,
                 const float* __restrict__ v, float* __restrict__ o)
{
    __shared__ float sQ[16][64];
    __shared__ float sK[64][65];   // pad: kills 16-way conflict on column reads
    __shared__ float sV[64][65];
    __shared__ float sP[16][65];
    __shared__ float sMl[16], sLl[16];

    int qt = blockIdx.x, h = blockIdx.y, b = blockIdx.z;
    int t0 = qt * 16;
    int tid = threadIdx.x;
    int r   = tid >> 4;      // query row in tile
    int c16 = tid & 15;
    int d0  = c16 * 4;
    int myT = t0 + r;

    for (int i = tid; i < 16 * 64; i += 256) {
        int rr = i >> 6, dd = i & 63;
        sQ[rr][dd] = q[((size_t)(b * TT + t0 + rr)) * CC + h * 64 + dd];
    }
    if (tid < 16) { sMl[tid] = -1e30f; sLl[tid] = 0.f; }
    float acc[4] = {0.f, 0.f, 0.f, 0.f};
    __syncthreads();

    for (int s0 = 0; s0 <= t0 + 15; s0 += 64) {
        for (int i = tid; i < 64 * 64; i += 256) {
            int rr = i >> 6, dd = i & 63;
            if (s0 + rr < TT) {
                size_t gi = ((size_t)(b * TT + s0 + rr)) * CC + h * 64 + dd;
                sK[rr][dd] = k[gi];
                sV[rr][dd] = v[gi];
            } else {
                sK[rr][dd] = 0.f;
                sV[rr][dd] = 0.f;
            }
        }
        __syncthreads();

        // scores
        float sc[4];
        float cmax = -1e30f;
        #pragma unroll
        for (int jj = 0; jj < 4; jj++) {
            int j = c16 + 16 * jj;
            float dot = 0.f;
            #pragma unroll
            for (int d = 0; d < 64; d++) dot = fmaf(sQ[r][d], sK[j][d], dot);
            dot *= 0.125f;                       // 1/sqrt(64)
            if (s0 + j > myT) dot = -1e30f;      // causal mask
            sc[jj] = dot;
            cmax = fmaxf(cmax, dot);
        }
        for (int off = 8; off; off >>= 1)
            cmax = fmaxf(cmax, __shfl_xor_sync(0xffffffffu, cmax, off));

        float oldm = sMl[r];
        float newm = fmaxf(oldm, cmax);
        float alpha = __expf(oldm - newm);

        float psum = 0.f;
        #pragma unroll
        for (int jj = 0; jj < 4; jj++) {
            float p = __expf(sc[jj] - newm);
            sP[r][c16 + 16 * jj] = p;
            psum += p;
        }
        for (int off = 8; off; off >>= 1)
            psum += __shfl_xor_sync(0xffffffffu, psum, off);
        if (c16 == 0) { sMl[r] = newm; sLl[r] = sLl[r] * alpha + psum; }
        __syncwarp();    // sP / sMl / sLl visibility within the row's warp half

        #pragma unroll
        for (int i = 0; i < 4; i++) acc[i] *= alpha;
        #pragma unroll
        for (int j = 0; j < 64; j++) {
            float p = sP[r][j];
            #pragma unroll
            for (int i = 0; i < 4; i++)
                acc[i] = fmaf(p, sV[j][d0 + i], acc[i]);
        }
        __syncthreads();
    }

    float linv = 1.f / sLl[r];
    size_t obase = ((size_t)(b * TT + myT)) * CC + h * 64 + d0;
    #pragma unroll
    for (int i = 0; i < 4; i++)
        o[obase + i] = acc[i] * linv;
}

// ---------------------------------------------------------------------------
// Per-row log-softmax NLL over V=50257 logits. One block per row.
// ---------------------------------------------------------------------------
__global__ void loss_row_kernel(const float* __restrict__ logits,
                                const int* __restrict__ tgt,
                                float* __restrict__ nll)
{
    int row = blockIdx.x;
    const float* lr = logits + (size_t)row * VV;
    int tid = threadIdx.x;
    __shared__ float sh[8];
    __shared__ float s_mx;

    float mx = -1e30f;
    for (int i = tid; i < VV; i += 256) mx = fmaxf(mx, lr[i]);
    for (int off = 16; off; off >>= 1)
        mx = fmaxf(mx, __shfl_xor_sync(0xffffffffu, mx, off));
    if ((tid & 31) == 0) sh[tid >> 5] = mx;
    __syncthreads();
    if (tid == 0) {
        float v = sh[0];
        for (int i = 1; i < 8; i++) v = fmaxf(v, sh[i]);
        s_mx = v;
    }
    __syncthreads();
    mx = s_mx;
    __syncthreads();

    float se = 0.f;
    for (int i = tid; i < VV; i += 256) se += __expf(lr[i] - mx);
    for (int off = 16; off; off >>= 1)
        se += __shfl_xor_sync(0xffffffffu, se, off);
    if ((tid & 31) == 0) sh[tid >> 5] = se;
    __syncthreads();
    if (tid == 0) {
        float t = 0.f;
        for (int i = 0; i < 8; i++) t += sh[i];
        nll[row] = -(lr[tgt[row]] - mx - logf(t));
    }
}

__global__ void loss_final_kernel(const float* __restrict__ nll,
                                  float* __restrict__ out)
{
    __shared__ float sh[8];
    int tid = threadIdx.x;
    float s = 0.f;
    for (int i = tid; i < MM; i += 256) s += nll[i];
    for (int off = 16; off; off >>= 1)
        s += __shfl_xor_sync(0xffffffffu, s, off);
    if ((tid & 31) == 0) sh[tid >> 5] = s;
    __syncthreads();
    if (tid == 0) {
        float t = 0.f;
        for (int i = 0; i < 8; i++) t += sh[i];
        out[0] = t / (float)MM;
    }
}

// ---------------------------------------------------------------------------
// Host launcher (graph-capturable: kernel launches only, default stream)
// ---------------------------------------------------------------------------
extern "C" void kernel_launch(void* const* d_in, const int* in_sizes, int n_in,
                              void* d_out, int out_size)
{
    const int*   idx     = (const int*)  d_in[0];
    const int*   targets = (const int*)  d_in[1];
    const float* tok_emb = (const float*)d_in[2];
    const float* pos_emb = (const float*)d_in[3];
    const float* ln1_w   = (const float*)d_in[4];
    const float* ln1_b   = (const float*)d_in[5];
    const float* ln2_w   = (const float*)d_in[6];
    const float* ln2_b   = (const float*)d_in[7];
    const float* Wq      = (const float*)d_in[8];
    const float* bq      = (const float*)d_in[9];
    const float* Wk      = (const float*)d_in[10];
    const float* bk      = (const float*)d_in[11];
    const float* Wv      = (const float*)d_in[12];
    const float* bv      = (const float*)d_in[13];
    const float* Wo      = (const float*)d_in[14];
    const float* bo      = (const float*)d_in[15];
    const float* W1      = (const float*)d_in[16];
    const float* b1      = (const float*)d_in[17];
    const float* W2      = (const float*)d_in[18];
    const float* b2      = (const float*)d_in[19];
    const float* lnf_w   = (const float*)d_in[20];
    const float* lnf_b   = (const float*)d_in[21];
    const float* head_w  = (const float*)d_in[22];
    float* out = (float*)d_out;

    void* p;
    cudaGetSymbolAddress(&p, g_x);   float* x   = (float*)p;
    cudaGetSymbolAddress(&p, g_h);   float* h   = (float*)p;
    cudaGetSymbolAddress(&p, g_q);   float* qb  = (float*)p;
    cudaGetSymbolAddress(&p, g_k);   float* kb  = (float*)p;
    cudaGetSymbolAddress(&p, g_v);   float* vb  = (float*)p;
    cudaGetSymbolAddress(&p, g_att); float* att = (float*)p;
    cudaGetSymbolAddress(&p, g_ffn); float* ffn = (float*)p;
    cudaGetSymbolAddress(&p, g_nll); float* nll = (float*)p;

    dim3 gemmCC((CC + 127) / 128, MM / 128);   // N=1024
    dim3 gemmCF((FF + 127) / 128, MM / 128);   // N=4096
    dim3 gemmCV((VV + 127) / 128, MM / 128);   // N=50257

    embed_kernel<<<MM, 256>>>(idx, tok_emb, pos_emb, x);

    for (int l = 0; l < LL; l++) {
        const float* wq = Wq + (size_t)l * CC * CC;
        const float* wk = Wk + (size_t)l * CC * CC;
        const float* wv = Wv + (size_t)l * CC * CC;
        const float* wo = Wo + (size_t)l * CC * CC;
        const float* w1 = W1 + (size_t)l * CC * FF;
        const float* w2 = W2 + (size_t)l * FF * CC;

        ln_kernel<<<MM, 256>>>(x, ln1_w + (size_t)l * CC, ln1_b + (size_t)l * CC, h);
        gemm_kernel<true, false, false><<<gemmCC, 256>>>(h, wq, bq + (size_t)l * CC, nullptr, qb, MM, CC, CC);
        gemm_kernel<true, false, false><<<gemmCC, 256>>>(h, wk, bk + (size_t)l * CC, nullptr, kb, MM, CC, CC);
        gemm_kernel<true, false, false><<<gemmCC, 256>>>(h, wv, bv + (size_t)l * CC, nullptr, vb, MM, CC, CC);
        attn_kernel<<<dim3(TT / 16, HH, BB), 256>>>(qb, kb, vb, att);
        gemm_kernel<true, true, false><<<gemmCC, 256>>>(att, wo, bo + (size_t)l * CC, x, x, MM, CC, CC);
        ln_kernel<<<MM, 256>>>(x, ln2_w + (size_t)l * CC, ln2_b + (size_t)l * CC, h);
        gemm_kernel<true, false, true><<<gemmCF, 256>>>(h, w1, b1 + (size_t)l * FF, nullptr, ffn, MM, FF, CC);
        gemm_kernel<true, true, false><<<gemmCC, 256>>>(ffn, w2, b2 + (size_t)l * CC, x, x, MM, CC, FF);
    }

    ln_kernel<<<MM, 256>>>(x, lnf_w, lnf_b, h);
    gemm_kernel<false, false, false><<<gemmCV, 256>>>(h, head_w, nullptr, nullptr, out, MM, VV, CC);

    loss_row_kernel<<<MM, 256>>>(out, targets, nll);
    size_t NL = (size_t)MM * VV;
    if ((size_t)out_size > NL)
        loss_final_kernel<<<1, 256>>>(nll, out + NL);
}

// round 13
// speedup vs baseline: 2.3354x; 2.3354x over previous
#include <cuda_runtime.h>
#include <cuda_bf16.h>
#include <math.h>
#include <stdint.h>

// Problem constants
#define BB 2
#define TT 1024
#define CC 1024
#define HH 16
#define LL 12
#define VV 50257
#define MM (BB*TT)      // 2048 token rows
#define FF (4*CC)       // 4096 MLP hidden

// ---------------------------------------------------------------------------
// Static device scratch (no allocation allowed). 16B-aligned: cp.async reads
// 16B vectors from these.
// ---------------------------------------------------------------------------
__device__ __align__(16) float g_x  [MM*CC];         // residual stream (fp32)
__device__ __align__(16) float g_q  [MM*CC];
__device__ __align__(16) float g_k  [MM*CC];
__device__ __align__(16) float g_v  [MM*CC];
__device__ __align__(16) float g_nll[MM];

// hi/lo bf16 activations (GEMM A operands)
__device__ __align__(16) __nv_bfloat16 g_h_hi  [MM*CC],         g_h_lo  [MM*CC];
__device__ __align__(16) __nv_bfloat16 g_att_hi[MM*CC],         g_att_lo[MM*CC];
__device__ __align__(16) __nv_bfloat16 g_ffn_hi[(size_t)MM*FF], g_ffn_lo[(size_t)MM*FF];

// Transposed bf16 hi/lo weight copies ([N,K] layout for B operand)
__device__ __align__(16) __nv_bfloat16 g_wq_hi[(size_t)LL*CC*CC], g_wq_lo[(size_t)LL*CC*CC];
__device__ __align__(16) __nv_bfloat16 g_wk_hi[(size_t)LL*CC*CC], g_wk_lo[(size_t)LL*CC*CC];
__device__ __align__(16) __nv_bfloat16 g_wv_hi[(size_t)LL*CC*CC], g_wv_lo[(size_t)LL*CC*CC];
__device__ __align__(16) __nv_bfloat16 g_wo_hi[(size_t)LL*CC*CC], g_wo_lo[(size_t)LL*CC*CC];
__device__ __align__(16) __nv_bfloat16 g_w1_hi[(size_t)LL*CC*FF], g_w1_lo[(size_t)LL*CC*FF];
__device__ __align__(16) __nv_bfloat16 g_w2_hi[(size_t)LL*FF*CC], g_w2_lo[(size_t)LL*FF*CC];
__device__ __align__(16) __nv_bfloat16 g_wh_hi[(size_t)VV*CC],    g_wh_lo[(size_t)VV*CC];

// ---------------------------------------------------------------------------
// PTX helpers (all baseline sm_80+ features: cp.async / ldmatrix / mma.sync)
// ---------------------------------------------------------------------------
__device__ __forceinline__ uint32_t smem_to_u32(const void* p) {
    uint32_t a;
    asm("{ .reg .u64 t; cvta.to.shared.u64 t, %1; cvt.u32.u64 %0, t; }"
        : "=r"(a) : "l"(p));
    return a;
}
#define CP_ASYNC16(dst, src, sz) \
    asm volatile("cp.async.cg.shared.global [%0], [%1], 16, %2;" \
                 :: "r"(dst), "l"(src), "r"(sz) : "memory")
#define CP_COMMIT() asm volatile("cp.async.commit_group;" ::: "memory")
#define CP_WAIT(n)  asm volatile("cp.async.wait_group %0;" :: "n"(n) : "memory")
#define LDSM4(r, addr) \
    asm volatile("ldmatrix.sync.aligned.m8n8.x4.shared.b16 {%0,%1,%2,%3}, [%4];" \
                 : "=r"((r)[0]), "=r"((r)[1]), "=r"((r)[2]), "=r"((r)[3]) \
                 : "r"(addr))
#define MMA16816(d, a, b) \
    asm volatile("mma.sync.aligned.m16n8k16.row.col.f32.bf16.bf16.f32 " \
                 "{%0,%1,%2,%3}, {%4,%5,%6,%7}, {%8,%9}, {%0,%1,%2,%3};" \
                 : "+f"((d)[0]), "+f"((d)[1]), "+f"((d)[2]), "+f"((d)[3]) \
                 : "r"((a)[0]), "r"((a)[1]), "r"((a)[2]), "r"((a)[3]), \
                   "r"((b)[0]), "r"((b)[1]))

__device__ __forceinline__ void split_bf16(float v, __nv_bfloat16& hi, __nv_bfloat16& lo) {
    hi = __float2bfloat16(v);
    lo = __float2bfloat16(v - __bfloat162float(hi));
}

// ---------------------------------------------------------------------------
// Weight conversion: W [K,N] fp32 -> transposed hi/lo bf16 [N,K]
// ---------------------------------------------------------------------------
__global__ void convw_kernel(const float* __restrict__ W,
                             __nv_bfloat16* __restrict__ hi,
                             __nv_bfloat16* __restrict__ lo,
                             int K, int N)
{
    __shared__ float t[32][33];
    size_t base = (size_t)blockIdx.z * K * N;
    int n0 = blockIdx.x * 32, k0 = blockIdx.y * 32;
    int tx = threadIdx.x, ty = threadIdx.y;
    #pragma unroll
    for (int j = 0; j < 32; j += 8) {
        int k = k0 + ty + j, n = n0 + tx;
        t[ty + j][tx] = (k < K && n < N) ? W[base + (size_t)k * N + n] : 0.f;
    }
    __syncthreads();
    #pragma unroll
    for (int j = 0; j < 32; j += 8) {
        int n = n0 + ty + j, k = k0 + tx;
        if (n < N && k < K) {
            float v = t[tx][ty + j];
            __nv_bfloat16 h, l;
            split_bf16(v, h, l);
            hi[base + (size_t)n * K + k] = h;
            lo[base + (size_t)n * K + k] = l;
        }
    }
}

// ---------------------------------------------------------------------------
// HMMA bf16x3 GEMM:
//   out[M,N] = A[M,K] @ Wt[N,K]  with A = Ahi+Alo, W = Bhi+Blo (drop lo*lo)
// 128x128x32 CTA tile, 8 warps (2x4), 64x32 warp tile, mma.m16n8k16,
// cp.async double-buffered smem (80B padded rows -> conflict-free ldmatrix).
// Epilogue: (+bias)(->GELU)(+res), out to fp32 OR to hi/lo bf16 (OUTHL).
// fp32 stores vectorize only when N is even (head N=50257 is odd ->
// odd-row float2 stores would be 4B-aligned only: the R8 "misaligned address").
// ---------------------------------------------------------------------------
#define GT_STRIDE 80                       // bytes per smem row (64 data + 16 pad)
#define GT_MAT    (128*GT_STRIDE)          // 10240 B per matrix tile
#define GT_STAGE  (4*GT_MAT)               // Ahi,Alo,Bhi,Blo = 40960 B
#define GEMM_SMEM (2*GT_STAGE)             // 81920 B

template<bool BIAS, bool RES, bool GELU, bool OUTHL>
__global__ __launch_bounds__(256, 1)
void gemm_mma_kernel(const __nv_bfloat16* __restrict__ Ahi,
                     const __nv_bfloat16* __restrict__ Alo,
                     const __nv_bfloat16* __restrict__ Bhi,
                     const __nv_bfloat16* __restrict__ Blo,
                     const float* __restrict__ bias,
                     const float* __restrict__ res,
                     float* __restrict__ out,
                     __nv_bfloat16* __restrict__ outHi,
                     __nv_bfloat16* __restrict__ outLo,
                     int M, int N, int K)
{
    extern __shared__ char smem[];
    const uint32_t sb = smem_to_u32(smem);
    const int tid = threadIdx.x;
    const int m0 = blockIdx.x * 128;
    const int n0 = blockIdx.y * 128;

    // --- cp.async loader setup: 8 x 16B chunks per thread per k-chunk ---
    const __nv_bfloat16* gsrc[8];
    uint32_t sdst[8];
    uint32_t csize[8];
    #pragma unroll
    for (int i = 0; i < 8; i++) {
        int c   = tid + 256 * i;
        int mat = c >> 9;            // 0:Ahi 1:Alo 2:Bhi 3:Blo
        int rem = c & 511;
        int row = rem >> 2;
        int seg = rem & 3;
        const __nv_bfloat16* base;
        int grow; bool ok = true;
        if      (mat == 0) { base = Ahi; grow = m0 + row; }
        else if (mat == 1) { base = Alo; grow = m0 + row; }
        else if (mat == 2) { base = Bhi; grow = n0 + row; ok = (grow < N); }
        else               { base = Blo; grow = n0 + row; ok = (grow < N); }
        gsrc[i]  = base + (size_t)(ok ? grow : 0) * K + seg * 8;
        sdst[i]  = sb + (uint32_t)(mat * GT_MAT + row * GT_STRIDE + seg * 16);
        csize[i] = ok ? 16u : 0u;    // src-size 0 => zero-fill
    }

    const int lane = tid & 31;
    const int wid  = tid >> 5;
    const int wm   = (wid & 1) * 64;     // warp M offset in tile
    const int wn   = (wid >> 1) * 32;    // warp N offset in tile

    float acc[4][4][4];
    #pragma unroll
    for (int mt = 0; mt < 4; mt++)
        #pragma unroll
        for (int nt = 0; nt < 4; nt++)
            #pragma unroll
            for (int i = 0; i < 4; i++) acc[mt][nt][i] = 0.f;

    const int NC = K >> 5;               // 32-wide fp-K chunks

    // prologue: stage 0, chunk 0
    #pragma unroll
    for (int i = 0; i < 8; i++) CP_ASYNC16(sdst[i], gsrc[i], csize[i]);
    CP_COMMIT();

    // precomputed ldmatrix lane addressing
    const uint32_t aRow  = (uint32_t)(wm + (lane & 15));          // + mt*16
    const uint32_t aKoff = (uint32_t)((lane >> 4) * 8);           // + ks*16
    const uint32_t bRow  = (uint32_t)(wn + (lane >> 4) * 8 + (lane & 7)); // + bt*16
    const uint32_t bKoff = (uint32_t)(((lane >> 3) & 1) * 8);

    #pragma unroll 1
    for (int c = 0; c < NC; c++) {
        if (c + 1 < NC) {
            int kc = (c + 1) << 5;
            uint32_t so = (uint32_t)(((c + 1) & 1) * GT_STAGE);
            #pragma unroll
            for (int i = 0; i < 8; i++)
                CP_ASYNC16(sdst[i] + so, gsrc[i] + kc, csize[i]);
            CP_COMMIT();
            CP_WAIT(1);
        } else {
            CP_WAIT(0);
        }
        __syncthreads();

        const uint32_t st = sb + (uint32_t)((c & 1) * GT_STAGE);
        #pragma unroll
        for (int ks = 0; ks < 2; ks++) {
            const uint32_t kb = (uint32_t)(ks * 16);
            uint32_t ah[4][4], al[4][4];
            #pragma unroll
            for (int mt = 0; mt < 4; mt++) {
                uint32_t ad = st + (aRow + mt * 16) * GT_STRIDE + (kb + aKoff) * 2;
                LDSM4(ah[mt], ad);
                LDSM4(al[mt], ad + GT_MAT);
            }
            uint32_t bh[2][4], bl[2][4];
            #pragma unroll
            for (int bt = 0; bt < 2; bt++) {
                uint32_t bd = st + 2 * GT_MAT + (bRow + bt * 16) * GT_STRIDE + (kb + bKoff) * 2;
                LDSM4(bh[bt], bd);
                LDSM4(bl[bt], bd + GT_MAT);
            }
            #pragma unroll
            for (int mt = 0; mt < 4; mt++) {
                #pragma unroll
                for (int nt = 0; nt < 4; nt++) {
                    const uint32_t* bhp = &bh[nt >> 1][(nt & 1) * 2];
                    const uint32_t* blp = &bl[nt >> 1][(nt & 1) * 2];
                    MMA16816(acc[mt][nt], ah[mt], bhp);
                    MMA16816(acc[mt][nt], ah[mt], blp);
                    MMA16816(acc[mt][nt], al[mt], bhp);
                }
            }
        }
        __syncthreads();
    }

    // --- Epilogue ---
    const bool evenN = ((N & 1) == 0);
    #pragma unroll
    for (int mt = 0; mt < 4; mt++) {
        int r0 = m0 + wm + mt * 16 + (lane >> 2);
        #pragma unroll
        for (int half = 0; half < 2; half++) {
            int row = r0 + half * 8;
            size_t rb = (size_t)row * N;
            #pragma unroll
            for (int nt = 0; nt < 4; nt++) {
                int col = n0 + wn + nt * 8 + (lane & 3) * 2;
                float v0 = acc[mt][nt][half * 2 + 0];
                float v1 = acc[mt][nt][half * 2 + 1];
                if (BIAS) { v0 += bias[col]; v1 += bias[col + 1]; }
                if (GELU) {
                    v0 = 0.5f * v0 * (1.0f + erff(v0 * 0.70710678118654752f));
                    v1 = 0.5f * v1 * (1.0f + erff(v1 * 0.70710678118654752f));
                }
                if (RES) { v0 += res[rb + col]; v1 += res[rb + col + 1]; }
                if (OUTHL) {
                    // only used with even N (CC/FF); rb+col even -> 4B aligned
                    __nv_bfloat16 h0, l0, h1, l1;
                    split_bf16(v0, h0, l0);
                    split_bf16(v1, h1, l1);
                    __nv_bfloat162 hv; hv.x = h0; hv.y = h1;
                    __nv_bfloat162 lv; lv.x = l0; lv.y = l1;
                    *(__nv_bfloat162*)(outHi + rb + col) = hv;
                    *(__nv_bfloat162*)(outLo + rb + col) = lv;
                } else {
                    if (evenN && (col + 1 < N)) {
                        float2 v; v.x = v0; v.y = v1;
                        *(float2*)(out + rb + col) = v;   // (rb+col) even -> 8B aligned
                    } else {
                        if (col < N)     out[rb + col]     = v0;
                        if (col + 1 < N) out[rb + col + 1] = v1;
                    }
                }
            }
        }
    }
}

// ---------------------------------------------------------------------------
// Embedding
// ---------------------------------------------------------------------------
__global__ void embed_kernel(const int* __restrict__ idx,
                             const float* __restrict__ tok,
                             const float* __restrict__ pos,
                             float* __restrict__ x)
{
    int row = blockIdx.x;
    int t   = row % TT;
    int id  = idx[row];
    const float* tr = tok + (size_t)id * CC;
    const float* pr = pos + (size_t)t  * CC;
    float* xr = x + (size_t)row * CC;
    for (int c = threadIdx.x; c < CC; c += blockDim.x)
        xr[c] = tr[c] + pr[c];
}

// ---------------------------------------------------------------------------
// LayerNorm -> hi/lo bf16 output (GEMM A format)
// ---------------------------------------------------------------------------
__global__ void ln_kernel(const float* __restrict__ x,
                          const float* __restrict__ w,
                          const float* __restrict__ b,
                          __nv_bfloat16* __restrict__ ohi,
                          __nv_bfloat16* __restrict__ olo)
{
    int row = blockIdx.x;
    const float* xr = x + (size_t)row * CC;
    int tid = threadIdx.x;
    float s = 0.f, ss = 0.f;
    for (int c = tid; c < CC; c += 256) { float v = xr[c]; s += v; ss += v * v; }
    for (int off = 16; off; off >>= 1) {
        s  += __shfl_xor_sync(0xffffffffu, s,  off);
        ss += __shfl_xor_sync(0xffffffffu, ss, off);
    }
    __shared__ float shs[8], shss[8];
    __shared__ float s_mu, s_rstd;
    if ((tid & 31) == 0) { shs[tid >> 5] = s; shss[tid >> 5] = ss; }
    __syncthreads();
    if (tid == 0) {
        float t1 = 0.f, t2 = 0.f;
        for (int i = 0; i < 8; i++) { t1 += shs[i]; t2 += shss[i]; }
        float mu  = t1 / (float)CC;
        float var = t2 / (float)CC - mu * mu;
        s_mu = mu;
        s_rstd = rsqrtf(var + 1e-5f);
    }
    __syncthreads();
    float mu = s_mu, rstd = s_rstd;
    size_t rb = (size_t)row * CC;
    for (int c = tid; c < CC; c += 256) {
        float y = (xr[c] - mu) * rstd * w[c] + b[c];
        __nv_bfloat16 h, l;
        split_bf16(y, h, l);
        ohi[rb + c] = h;
        olo[rb + c] = l;
    }
}

// ---------------------------------------------------------------------------
// Causal flash attention (fp32, online softmax); emits hi/lo bf16 output
// ---------------------------------------------------------------------------
__global__ __launch_bounds__(256)
void attn_kernel(const float* __restrict__ q, const float* __restrict__ k,
                 const float* __restrict__ v,
                 __nv_bfloat16* __restrict__ ohi,
                 __nv_bfloat16* __restrict__ olo)
{
    __shared__ float sQ[16][64];
    __shared__ float sK[64][65];
    __shared__ float sV[64][65];
    __shared__ float sP[16][65];
    __shared__ float sMl[16], sLl[16];

    int qt = blockIdx.x, h = blockIdx.y, b = blockIdx.z;
    int t0 = qt * 16;
    int tid = threadIdx.x;
    int r   = tid >> 4;
    int c16 = tid & 15;
    int d0  = c16 * 4;
    int myT = t0 + r;

    for (int i = tid; i < 16 * 64; i += 256) {
        int rr = i >> 6, dd = i & 63;
        sQ[rr][dd] = q[((size_t)(b * TT + t0 + rr)) * CC + h * 64 + dd];
    }
    if (tid < 16) { sMl[tid] = -1e30f; sLl[tid] = 0.f; }
    float acc[4] = {0.f, 0.f, 0.f, 0.f};
    __syncthreads();

    for (int s0 = 0; s0 <= t0 + 15; s0 += 64) {
        for (int i = tid; i < 64 * 64; i += 256) {
            int rr = i >> 6, dd = i & 63;
            if (s0 + rr < TT) {
                size_t gi = ((size_t)(b * TT + s0 + rr)) * CC + h * 64 + dd;
                sK[rr][dd] = k[gi];
                sV[rr][dd] = v[gi];
            } else {
                sK[rr][dd] = 0.f;
                sV[rr][dd] = 0.f;
            }
        }
        __syncthreads();

        float sc[4];
        float cmax = -1e30f;
        #pragma unroll
        for (int jj = 0; jj < 4; jj++) {
            int j = c16 + 16 * jj;
            float dot = 0.f;
            #pragma unroll
            for (int d = 0; d < 64; d++) dot = fmaf(sQ[r][d], sK[j][d], dot);
            dot *= 0.125f;
            if (s0 + j > myT) dot = -1e30f;
            sc[jj] = dot;
            cmax = fmaxf(cmax, dot);
        }
        for (int off = 8; off; off >>= 1)
            cmax = fmaxf(cmax, __shfl_xor_sync(0xffffffffu, cmax, off));

        float oldm = sMl[r];
        float newm = fmaxf(oldm, cmax);
        float alpha = __expf(oldm - newm);

        float psum = 0.f;
        #pragma unroll
        for (int jj = 0; jj < 4; jj++) {
            float p = __expf(sc[jj] - newm);
            sP[r][c16 + 16 * jj] = p;
            psum += p;
        }
        for (int off = 8; off; off >>= 1)
            psum += __shfl_xor_sync(0xffffffffu, psum, off);
        if (c16 == 0) { sMl[r] = newm; sLl[r] = sLl[r] * alpha + psum; }
        __syncwarp();

        #pragma unroll
        for (int i = 0; i < 4; i++) acc[i] *= alpha;
        #pragma unroll
        for (int j = 0; j < 64; j++) {
            float p = sP[r][j];
            #pragma unroll
            for (int i = 0; i < 4; i++)
                acc[i] = fmaf(p, sV[j][d0 + i], acc[i]);
        }
        __syncthreads();
    }

    float linv = 1.f / sLl[r];
    size_t obase = ((size_t)(b * TT + myT)) * CC + h * 64 + d0;
    #pragma unroll
    for (int i = 0; i < 4; i++) {
        float val = acc[i] * linv;
        __nv_bfloat16 hh, ll;
        split_bf16(val, hh, ll);
        ohi[obase + i] = hh;
        olo[obase + i] = ll;
    }
}

// ---------------------------------------------------------------------------
// Loss
// ---------------------------------------------------------------------------
__global__ void loss_row_kernel(const float* __restrict__ logits,
                                const int* __restrict__ tgt,
                                float* __restrict__ nll)
{
    int row = blockIdx.x;
    const float* lr = logits + (size_t)row * VV;
    int tid = threadIdx.x;
    __shared__ float sh[8];
    __shared__ float s_mx;

    float mx = -1e30f;
    for (int i = tid; i < VV; i += 256) mx = fmaxf(mx, lr[i]);
    for (int off = 16; off; off >>= 1)
        mx = fmaxf(mx, __shfl_xor_sync(0xffffffffu, mx, off));
    if ((tid & 31) == 0) sh[tid >> 5] = mx;
    __syncthreads();
    if (tid == 0) {
        float v = sh[0];
        for (int i = 1; i < 8; i++) v = fmaxf(v, sh[i]);
        s_mx = v;
    }
    __syncthreads();
    mx = s_mx;
    __syncthreads();

    float se = 0.f;
    for (int i = tid; i < VV; i += 256) se += __expf(lr[i] - mx);
    for (int off = 16; off; off >>= 1)
        se += __shfl_xor_sync(0xffffffffu, se, off);
    if ((tid & 31) == 0) sh[tid >> 5] = se;
    __syncthreads();
    if (tid == 0) {
        float t = 0.f;
        for (int i = 0; i < 8; i++) t += sh[i];
        nll[row] = -(lr[tgt[row]] - mx - logf(t));
    }
}

__global__ void loss_final_kernel(const float* __restrict__ nll,
                                  float* __restrict__ out)
{
    __shared__ float sh[8];
    int tid = threadIdx.x;
    float s = 0.f;
    for (int i = tid; i < MM; i += 256) s += nll[i];
    for (int off = 16; off; off >>= 1)
        s += __shfl_xor_sync(0xffffffffu, s, off);
    if ((tid & 31) == 0) sh[tid >> 5] = s;
    __syncthreads();
    if (tid == 0) {
        float t = 0.f;
        for (int i = 0; i < 8; i++) t += sh[i];
        out[0] = t / (float)MM;
    }
}

// ---------------------------------------------------------------------------
// Host launcher (graph-capturable: kernel launches only)
// ---------------------------------------------------------------------------
extern "C" void kernel_launch(void* const* d_in, const int* in_sizes, int n_in,
                              void* d_out, int out_size)
{
    const int*   idx     = (const int*)  d_in[0];
    const int*   targets = (const int*)  d_in[1];
    const float* tok_emb = (const float*)d_in[2];
    const float* pos_emb = (const float*)d_in[3];
    const float* ln1_w   = (const float*)d_in[4];
    const float* ln1_b   = (const float*)d_in[5];
    const float* ln2_w   = (const float*)d_in[6];
    const float* ln2_b   = (const float*)d_in[7];
    const float* Wq      = (const float*)d_in[8];
    const float* bq      = (const float*)d_in[9];
    const float* Wk      = (const float*)d_in[10];
    const float* bk      = (const float*)d_in[11];
    const float* Wv      = (const float*)d_in[12];
    const float* bv      = (const float*)d_in[13];
    const float* Wo      = (const float*)d_in[14];
    const float* bo      = (const float*)d_in[15];
    const float* W1      = (const float*)d_in[16];
    const float* b1      = (const float*)d_in[17];
    const float* W2      = (const float*)d_in[18];
    const float* b2      = (const float*)d_in[19];
    const float* lnf_w   = (const float*)d_in[20];
    const float* lnf_b   = (const float*)d_in[21];
    const float* head_w  = (const float*)d_in[22];
    float* out = (float*)d_out;

    void* p;
    cudaGetSymbolAddress(&p, g_x);   float* x   = (float*)p;
    cudaGetSymbolAddress(&p, g_q);   float* qb  = (float*)p;
    cudaGetSymbolAddress(&p, g_k);   float* kb  = (float*)p;
    cudaGetSymbolAddress(&p, g_v);   float* vb  = (float*)p;
    cudaGetSymbolAddress(&p, g_nll); float* nll = (float*)p;

    __nv_bfloat16 *h_hi, *h_lo, *att_hi, *att_lo, *ffn_hi, *ffn_lo;
    cudaGetSymbolAddress(&p, g_h_hi);   h_hi   = (__nv_bfloat16*)p;
    cudaGetSymbolAddress(&p, g_h_lo);   h_lo   = (__nv_bfloat16*)p;
    cudaGetSymbolAddress(&p, g_att_hi); att_hi = (__nv_bfloat16*)p;
    cudaGetSymbolAddress(&p, g_att_lo); att_lo = (__nv_bfloat16*)p;
    cudaGetSymbolAddress(&p, g_ffn_hi); ffn_hi = (__nv_bfloat16*)p;
    cudaGetSymbolAddress(&p, g_ffn_lo); ffn_lo = (__nv_bfloat16*)p;

    __nv_bfloat16 *wq_hi, *wq_lo, *wk_hi, *wk_lo, *wv_hi, *wv_lo, *wo_hi, *wo_lo;
    __nv_bfloat16 *w1_hi, *w1_lo, *w2_hi, *w2_lo, *wh_hi, *wh_lo;
    cudaGetSymbolAddress(&p, g_wq_hi); wq_hi = (__nv_bfloat16*)p;
    cudaGetSymbolAddress(&p, g_wq_lo); wq_lo = (__nv_bfloat16*)p;
    cudaGetSymbolAddress(&p, g_wk_hi); wk_hi = (__nv_bfloat16*)p;
    cudaGetSymbolAddress(&p, g_wk_lo); wk_lo = (__nv_bfloat16*)p;
    cudaGetSymbolAddress(&p, g_wv_hi); wv_hi = (__nv_bfloat16*)p;
    cudaGetSymbolAddress(&p, g_wv_lo); wv_lo = (__nv_bfloat16*)p;
    cudaGetSymbolAddress(&p, g_wo_hi); wo_hi = (__nv_bfloat16*)p;
    cudaGetSymbolAddress(&p, g_wo_lo); wo_lo = (__nv_bfloat16*)p;
    cudaGetSymbolAddress(&p, g_w1_hi); w1_hi = (__nv_bfloat16*)p;
    cudaGetSymbolAddress(&p, g_w1_lo); w1_lo = (__nv_bfloat16*)p;
    cudaGetSymbolAddress(&p, g_w2_hi); w2_hi = (__nv_bfloat16*)p;
    cudaGetSymbolAddress(&p, g_w2_lo); w2_lo = (__nv_bfloat16*)p;
    cudaGetSymbolAddress(&p, g_wh_hi); wh_hi = (__nv_bfloat16*)p;
    cudaGetSymbolAddress(&p, g_wh_lo); wh_lo = (__nv_bfloat16*)p;

    cudaFuncSetAttribute(gemm_mma_kernel<true,  false, false, false>,
                         cudaFuncAttributeMaxDynamicSharedMemorySize, GEMM_SMEM);
    cudaFuncSetAttribute(gemm_mma_kernel<true,  true,  false, false>,
                         cudaFuncAttributeMaxDynamicSharedMemorySize, GEMM_SMEM);
    cudaFuncSetAttribute(gemm_mma_kernel<true,  false, true,  true>,
                         cudaFuncAttributeMaxDynamicSharedMemorySize, GEMM_SMEM);
    cudaFuncSetAttribute(gemm_mma_kernel<false, false, false, false>,
                         cudaFuncAttributeMaxDynamicSharedMemorySize, GEMM_SMEM);

    // Weight conversion (transpose + bf16 hi/lo split)
    dim3 cb(32, 8);
    convw_kernel<<<dim3(CC / 32, CC / 32, LL), cb>>>(Wq, wq_hi, wq_lo, CC, CC);
    convw_kernel<<<dim3(CC / 32, CC / 32, LL), cb>>>(Wk, wk_hi, wk_lo, CC, CC);
    convw_kernel<<<dim3(CC / 32, CC / 32, LL), cb>>>(Wv, wv_hi, wv_lo, CC, CC);
    convw_kernel<<<dim3(CC / 32, CC / 32, LL), cb>>>(Wo, wo_hi, wo_lo, CC, CC);
    convw_kernel<<<dim3(FF / 32, CC / 32, LL), cb>>>(W1, w1_hi, w1_lo, CC, FF);
    convw_kernel<<<dim3(CC / 32, FF / 32, LL), cb>>>(W2, w2_hi, w2_lo, FF, CC);
    convw_kernel<<<dim3((VV + 31) / 32, CC / 32, 1), cb>>>(head_w, wh_hi, wh_lo, CC, VV);

    dim3 gCC(MM / 128, CC / 128);            // (16, 8)
    dim3 gCF(MM / 128, FF / 128);            // (16, 32)
    dim3 gCV(MM / 128, (VV + 127) / 128);    // (16, 393)

    embed_kernel<<<MM, 256>>>(idx, tok_emb, pos_emb, x);

    for (int l = 0; l < LL; l++) {
        size_t oCC = (size_t)l * CC * CC;
        size_t oCF = (size_t)l * CC * FF;

        ln_kernel<<<MM, 256>>>(x, ln1_w + (size_t)l * CC, ln1_b + (size_t)l * CC, h_hi, h_lo);
        gemm_mma_kernel<true, false, false, false><<<gCC, 256, GEMM_SMEM>>>(
            h_hi, h_lo, wq_hi + oCC, wq_lo + oCC, bq + (size_t)l * CC,
            nullptr, qb, nullptr, nullptr, MM, CC, CC);
        gemm_mma_kernel<true, false, false, false><<<gCC, 256, GEMM_SMEM>>>(
            h_hi, h_lo, wk_hi + oCC, wk_lo + oCC, bk + (size_t)l * CC,
            nullptr, kb, nullptr, nullptr, MM, CC, CC);
        gemm_mma_kernel<true, false, false, false><<<gCC, 256, GEMM_SMEM>>>(
            h_hi, h_lo, wv_hi + oCC, wv_lo + oCC, bv + (size_t)l * CC,
            nullptr, vb, nullptr, nullptr, MM, CC, CC);
        attn_kernel<<<dim3(TT / 16, HH, BB), 256>>>(qb, kb, vb, att_hi, att_lo);
        gemm_mma_kernel<true, true, false, false><<<gCC, 256, GEMM_SMEM>>>(
            att_hi, att_lo, wo_hi + oCC, wo_lo + oCC, bo + (size_t)l * CC,
            x, x, nullptr, nullptr, MM, CC, CC);
        ln_kernel<<<MM, 256>>>(x, ln2_w + (size_t)l * CC, ln2_b + (size_t)l * CC, h_hi, h_lo);
        gemm_mma_kernel<true, false, true, true><<<gCF, 256, GEMM_SMEM>>>(
            h_hi, h_lo, w1_hi + oCF, w1_lo + oCF, b1 + (size_t)l * FF,
            nullptr, nullptr, ffn_hi, ffn_lo, MM, FF, CC);
        gemm_mma_kernel<true, true, false, false><<<gCC, 256, GEMM_SMEM>>>(
            ffn_hi, ffn_lo, w2_hi + oCF, w2_lo + oCF, b2 + (size_t)l * CC,
            x, x, nullptr, nullptr, MM, CC, FF);
    }

    ln_kernel<<<MM, 256>>>(x, lnf_w, lnf_b, h_hi, h_lo);
    gemm_mma_kernel<false, false, false, false><<<gCV, 256, GEMM_SMEM>>>(
        h_hi, h_lo, wh_hi, wh_lo, nullptr, nullptr, out, nullptr, nullptr, MM, VV, CC);

    loss_row_kernel<<<MM, 256>>>(out, targets, nll);
    size_t NL = (size_t)MM * VV;
    if ((size_t)out_size > NL)
        loss_final_kernel<<<1, 256>>>(nll, out + NL);
}

// round 15
// speedup vs baseline: 3.4441x; 1.4748x over previous
#include <cuda_runtime.h>
#include <cuda_bf16.h>
#include <math.h>
#include <stdint.h>

// Problem constants
#define BB 2
#define TT 1024
#define CC 1024
#define HH 16
#define LL 12
#define VV 50257
#define MM (BB*TT)      // 2048 token rows
#define FF (4*CC)       // 4096 MLP hidden

// ---------------------------------------------------------------------------
// Static device scratch (no allocation allowed). 16B-aligned for cp.async.
// ---------------------------------------------------------------------------
__device__ __align__(16) float g_x  [MM*CC];         // residual stream (fp32)
__device__ __align__(16) float g_nll[MM];

// hi/lo bf16 activations
__device__ __align__(16) __nv_bfloat16 g_h_hi  [MM*CC],         g_h_lo  [MM*CC];
__device__ __align__(16) __nv_bfloat16 g_q_hi  [MM*CC],         g_q_lo  [MM*CC];
__device__ __align__(16) __nv_bfloat16 g_k_hi  [MM*CC],         g_k_lo  [MM*CC];
__device__ __align__(16) __nv_bfloat16 g_vt_hi [MM*CC],         g_vt_lo [MM*CC];  // [B,H,64,T]
__device__ __align__(16) __nv_bfloat16 g_att_hi[MM*CC],         g_att_lo[MM*CC];
__device__ __align__(16) __nv_bfloat16 g_ffn_hi[(size_t)MM*FF], g_ffn_lo[(size_t)MM*FF];

// Transposed bf16 hi/lo weight copies ([N,K] layout for B operand)
__device__ __align__(16) __nv_bfloat16 g_wq_hi[(size_t)LL*CC*CC], g_wq_lo[(size_t)LL*CC*CC];
__device__ __align__(16) __nv_bfloat16 g_wk_hi[(size_t)LL*CC*CC], g_wk_lo[(size_t)LL*CC*CC];
__device__ __align__(16) __nv_bfloat16 g_wv_hi[(size_t)LL*CC*CC], g_wv_lo[(size_t)LL*CC*CC];
__device__ __align__(16) __nv_bfloat16 g_wo_hi[(size_t)LL*CC*CC], g_wo_lo[(size_t)LL*CC*CC];
__device__ __align__(16) __nv_bfloat16 g_w1_hi[(size_t)LL*CC*FF], g_w1_lo[(size_t)LL*CC*FF];
__device__ __align__(16) __nv_bfloat16 g_w2_hi[(size_t)LL*FF*CC], g_w2_lo[(size_t)LL*FF*CC];
__device__ __align__(16) __nv_bfloat16 g_wh_hi[(size_t)VV*CC],    g_wh_lo[(size_t)VV*CC];

// ---------------------------------------------------------------------------
// PTX helpers
// ---------------------------------------------------------------------------
__device__ __forceinline__ uint32_t smem_to_u32(const void* p) {
    uint32_t a;
    asm("{ .reg .u64 t; cvta.to.shared.u64 t, %1; cvt.u32.u64 %0, t; }"
        : "=r"(a) : "l"(p));
    return a;
}
#define CP_ASYNC16(dst, src, sz) \
    asm volatile("cp.async.cg.shared.global [%0], [%1], 16, %2;" \
                 :: "r"(dst), "l"(src), "r"(sz) : "memory")
#define CP_COMMIT() asm volatile("cp.async.commit_group;" ::: "memory")
#define CP_WAIT(n)  asm volatile("cp.async.wait_group %0;" :: "n"(n) : "memory")
#define LDSM4(r, addr) \
    asm volatile("ldmatrix.sync.aligned.m8n8.x4.shared.b16 {%0,%1,%2,%3}, [%4];" \
                 : "=r"((r)[0]), "=r"((r)[1]), "=r"((r)[2]), "=r"((r)[3]) \
                 : "r"(addr))
#define MMA16816(d, a, b) \
    asm volatile("mma.sync.aligned.m16n8k16.row.col.f32.bf16.bf16.f32 " \
                 "{%0,%1,%2,%3}, {%4,%5,%6,%7}, {%8,%9}, {%0,%1,%2,%3};" \
                 : "+f"((d)[0]), "+f"((d)[1]), "+f"((d)[2]), "+f"((d)[3]) \
                 : "r"((a)[0]), "r"((a)[1]), "r"((a)[2]), "r"((a)[3]), \
                   "r"((b)[0]), "r"((b)[1]))

__device__ __forceinline__ void split_bf16(float v, __nv_bfloat16& hi, __nv_bfloat16& lo) {
    hi = __float2bfloat16(v);
    lo = __float2bfloat16(v - __bfloat162float(hi));
}
__device__ __forceinline__ uint32_t pack_split(float v0, float v1, uint32_t& loOut) {
    __nv_bfloat16 h0, l0, h1, l1;
    split_bf16(v0, h0, l0); split_bf16(v1, h1, l1);
    __nv_bfloat162 hv; hv.x = h0; hv.y = h1;
    __nv_bfloat162 lv; lv.x = l0; lv.y = l1;
    loOut = *reinterpret_cast<uint32_t*>(&lv);
    return *reinterpret_cast<uint32_t*>(&hv);
}

// Fast exp for x <= 0 (FMA-pipe; avoids the MUFU throughput wall).
// exp(x) = 2^k * 2^f, f in [-0.5,0.5], Taylor in f*ln2; rel err ~2e-6.
__device__ __forceinline__ float fast_exp(float x) {
    x = fmaxf(x, -87.0f);
    float t = x * 1.4426950408889634f;
    float k = floorf(t + 0.5f);
    float f = t - k;
    float p = fmaf(f, 0.00133335581f, 0.00961812910f);
    p = fmaf(f, p, 0.0555041087f);
    p = fmaf(f, p, 0.240226507f);
    p = fmaf(f, p, 0.693147180f);
    p = fmaf(f, p, 1.0f);
    return p * __int_as_float(((int)k + 127) << 23);
}

// ---------------------------------------------------------------------------
// Weight conversion: W [K,N] fp32 -> transposed hi/lo bf16 [N,K]
// ---------------------------------------------------------------------------
__global__ void convw_kernel(const float* __restrict__ W,
                             __nv_bfloat16* __restrict__ hi,
                             __nv_bfloat16* __restrict__ lo,
                             int K, int N)
{
    __shared__ float t[32][33];
    size_t base = (size_t)blockIdx.z * K * N;
    int n0 = blockIdx.x * 32, k0 = blockIdx.y * 32;
    int tx = threadIdx.x, ty = threadIdx.y;
    #pragma unroll
    for (int j = 0; j < 32; j += 8) {
        int k = k0 + ty + j, n = n0 + tx;
        t[ty + j][tx] = (k < K && n < N) ? W[base + (size_t)k * N + n] : 0.f;
    }
    __syncthreads();
    #pragma unroll
    for (int j = 0; j < 32; j += 8) {
        int n = n0 + ty + j, k = k0 + tx;
        if (n < N && k < K) {
            float v = t[tx][ty + j];
            __nv_bfloat16 h, l;
            split_bf16(v, h, l);
            hi[base + (size_t)n * K + k] = h;
            lo[base + (size_t)n * K + k] = l;
        }
    }
}

// ---------------------------------------------------------------------------
// HMMA bf16x3 GEMM, 128x128x32 tile, 3-stage cp.async pipeline.
// Outputs: fp32 (+bias/GELU/res), hi/lo bf16 (OUTHL), or transposed hi/lo
// bf16 [B,H,64,T] (OUTVT, for V).
// ---------------------------------------------------------------------------
#define GT_STRIDE 80
#define GT_MAT    (128*GT_STRIDE)
#define GT_STAGE  (4*GT_MAT)               // 40960
#define GEMM_SMEM (3*GT_STAGE)             // 122880

template<bool BIAS, bool RES, bool GELU, bool OUTHL, bool OUTVT>
__global__ __launch_bounds__(256, 1)
void gemm_mma_kernel(const __nv_bfloat16* __restrict__ Ahi,
                     const __nv_bfloat16* __restrict__ Alo,
                     const __nv_bfloat16* __restrict__ Bhi,
                     const __nv_bfloat16* __restrict__ Blo,
                     const float* __restrict__ bias,
                     const float* __restrict__ res,
                     float* __restrict__ out,
                     __nv_bfloat16* __restrict__ outHi,
                     __nv_bfloat16* __restrict__ outLo,
                     int M, int N, int K)
{
    extern __shared__ char smem[];
    const uint32_t sb = smem_to_u32(smem);
    const int tid = threadIdx.x;
    const int m0 = blockIdx.x * 128;
    const int n0 = blockIdx.y * 128;

    const __nv_bfloat16* gsrc[8];
    uint32_t sdst[8];
    uint32_t csize[8];
    #pragma unroll
    for (int i = 0; i < 8; i++) {
        int c   = tid + 256 * i;
        int mat = c >> 9;
        int rem = c & 511;
        int row = rem >> 2;
        int seg = rem & 3;
        const __nv_bfloat16* base;
        int grow; bool ok = true;
        if      (mat == 0) { base = Ahi; grow = m0 + row; }
        else if (mat == 1) { base = Alo; grow = m0 + row; }
        else if (mat == 2) { base = Bhi; grow = n0 + row; ok = (grow < N); }
        else               { base = Blo; grow = n0 + row; ok = (grow < N); }
        gsrc[i]  = base + (size_t)(ok ? grow : 0) * K + seg * 8;
        sdst[i]  = sb + (uint32_t)(mat * GT_MAT + row * GT_STRIDE + seg * 16);
        csize[i] = ok ? 16u : 0u;
    }

    const int lane = tid & 31;
    const int wid  = tid >> 5;
    const int wm   = (wid & 1) * 64;
    const int wn   = (wid >> 1) * 32;

    float acc[4][4][4];
    #pragma unroll
    for (int mt = 0; mt < 4; mt++)
        #pragma unroll
        for (int nt = 0; nt < 4; nt++)
            #pragma unroll
            for (int i = 0; i < 4; i++) acc[mt][nt][i] = 0.f;

    const int NC = K >> 5;

    // prologue: stages 0 and 1
    #pragma unroll
    for (int i = 0; i < 8; i++) CP_ASYNC16(sdst[i], gsrc[i], csize[i]);
    CP_COMMIT();
    if (NC > 1) {
        #pragma unroll
        for (int i = 0; i < 8; i++) CP_ASYNC16(sdst[i] + GT_STAGE, gsrc[i] + 32, csize[i]);
        CP_COMMIT();
    }

    const uint32_t aRow  = (uint32_t)(wm + (lane & 15));
    const uint32_t aKoff = (uint32_t)((lane >> 4) * 8);
    const uint32_t bRow  = (uint32_t)(wn + (lane >> 4) * 8 + (lane & 7));
    const uint32_t bKoff = (uint32_t)(((lane >> 3) & 1) * 8);

    int stageIdx = 0;
    #pragma unroll 1
    for (int c = 0; c < NC; c++) {
        if (c + 2 < NC) {
            // issue chunk c+2 into stage (c+2)%3 (free: compute c-1 done)
            int s2 = stageIdx + 2; if (s2 >= 3) s2 -= 3;
            uint32_t so = (uint32_t)(s2 * GT_STAGE);
            int kc = (c + 2) << 5;
            #pragma unroll
            for (int i = 0; i < 8; i++)
                CP_ASYNC16(sdst[i] + so, gsrc[i] + kc, csize[i]);
            CP_COMMIT();
            CP_WAIT(2);
        } else if (c + 1 < NC) {
            CP_WAIT(1);
        } else {
            CP_WAIT(0);
        }
        __syncthreads();

        const uint32_t st = sb + (uint32_t)(stageIdx * GT_STAGE);
        #pragma unroll
        for (int ks = 0; ks < 2; ks++) {
            const uint32_t kb = (uint32_t)(ks * 16);
            uint32_t ah[4][4], al[4][4];
            #pragma unroll
            for (int mt = 0; mt < 4; mt++) {
                uint32_t ad = st + (aRow + mt * 16) * GT_STRIDE + (kb + aKoff) * 2;
                LDSM4(ah[mt], ad);
                LDSM4(al[mt], ad + GT_MAT);
            }
            uint32_t bh[2][4], bl[2][4];
            #pragma unroll
            for (int bt = 0; bt < 2; bt++) {
                uint32_t bd = st + 2 * GT_MAT + (bRow + bt * 16) * GT_STRIDE + (kb + bKoff) * 2;
                LDSM4(bh[bt], bd);
                LDSM4(bl[bt], bd + GT_MAT);
            }
            #pragma unroll
            for (int mt = 0; mt < 4; mt++) {
                #pragma unroll
                for (int nt = 0; nt < 4; nt++) {
                    const uint32_t* bhp = &bh[nt >> 1][(nt & 1) * 2];
                    const uint32_t* blp = &bl[nt >> 1][(nt & 1) * 2];
                    MMA16816(acc[mt][nt], ah[mt], bhp);
                    MMA16816(acc[mt][nt], ah[mt], blp);
                    MMA16816(acc[mt][nt], al[mt], bhp);
                }
            }
        }
        __syncthreads();
        stageIdx++; if (stageIdx == 3) stageIdx = 0;
    }

    // --- Epilogue ---
    const bool evenN = ((N & 1) == 0);
    #pragma unroll
    for (int mt = 0; mt < 4; mt++) {
        int r0 = m0 + wm + mt * 16 + (lane >> 2);
        #pragma unroll
        for (int half = 0; half < 2; half++) {
            int row = r0 + half * 8;
            size_t rb = (size_t)row * N;
            #pragma unroll
            for (int nt = 0; nt < 4; nt++) {
                int col = n0 + wn + nt * 8 + (lane & 3) * 2;
                float v0 = acc[mt][nt][half * 2 + 0];
                float v1 = acc[mt][nt][half * 2 + 1];
                if (BIAS) { v0 += bias[col]; v1 += bias[col + 1]; }
                if (GELU) {
                    v0 = 0.5f * v0 * (1.0f + erff(v0 * 0.70710678118654752f));
                    v1 = 0.5f * v1 * (1.0f + erff(v1 * 0.70710678118654752f));
                }
                if (RES) { v0 += res[rb + col]; v1 += res[rb + col + 1]; }
                if (OUTVT) {
                    // transposed store: vt[b][head][d][t], col even => d even
                    int bb = row >> 10, t = row & (TT - 1);
                    int head = col >> 6, d = col & 63;
                    size_t i0 = (((size_t)bb * HH + head) * 64 + d) * (size_t)TT + t;
                    __nv_bfloat16 h0, l0, h1, l1;
                    split_bf16(v0, h0, l0); split_bf16(v1, h1, l1);
                    outHi[i0] = h0;      outLo[i0] = l0;
                    outHi[i0 + TT] = h1; outLo[i0 + TT] = l1;
                } else if (OUTHL) {
                    uint32_t lv, hv = pack_split(v0, v1, lv);
                    *(uint32_t*)(outHi + rb + col) = hv;
                    *(uint32_t*)(outLo + rb + col) = lv;
                } else {
                    if (evenN && (col + 1 < N)) {
                        float2 v; v.x = v0; v.y = v1;
                        *(float2*)(out + rb + col) = v;
                    } else {
                        if (col < N)     out[rb + col]     = v0;
                        if (col + 1 < N) out[rb + col + 1] = v1;
                    }
                }
            }
        }
    }
}

// ---------------------------------------------------------------------------
// Embedding
// ---------------------------------------------------------------------------
__global__ void embed_kernel(const int* __restrict__ idx,
                             const float* __restrict__ tok,
                             const float* __restrict__ pos,
                             float* __restrict__ x)
{
    int row = blockIdx.x;
    int t   = row % TT;
    int id  = idx[row];
    const float* tr = tok + (size_t)id * CC;
    const float* pr = pos + (size_t)t  * CC;
    float* xr = x + (size_t)row * CC;
    for (int c = threadIdx.x; c < CC; c += blockDim.x)
        xr[c] = tr[c] + pr[c];
}

// ---------------------------------------------------------------------------
// LayerNorm -> hi/lo bf16
// ---------------------------------------------------------------------------
__global__ void ln_kernel(const float* __restrict__ x,
                          const float* __restrict__ w,
                          const float* __restrict__ b,
                          __nv_bfloat16* __restrict__ ohi,
                          __nv_bfloat16* __restrict__ olo)
{
    int row = blockIdx.x;
    const float* xr = x + (size_t)row * CC;
    int tid = threadIdx.x;
    float s = 0.f, ss = 0.f;
    for (int c = tid; c < CC; c += 256) { float v = xr[c]; s += v; ss += v * v; }
    for (int off = 16; off; off >>= 1) {
        s  += __shfl_xor_sync(0xffffffffu, s,  off);
        ss += __shfl_xor_sync(0xffffffffu, ss, off);
    }
    __shared__ float shs[8], shss[8];
    __shared__ float s_mu, s_rstd;
    if ((tid & 31) == 0) { shs[tid >> 5] = s; shss[tid >> 5] = ss; }
    __syncthreads();
    if (tid == 0) {
        float t1 = 0.f, t2 = 0.f;
        for (int i = 0; i < 8; i++) { t1 += shs[i]; t2 += shss[i]; }
        float mu  = t1 / (float)CC;
        float var = t2 / (float)CC - mu * mu;
        s_mu = mu;
        s_rstd = rsqrtf(var + 1e-5f);
    }
    __syncthreads();
    float mu = s_mu, rstd = s_rstd;
    size_t rb = (size_t)row * CC;
    for (int c = tid; c < CC; c += 256) {
        float y = (xr[c] - mu) * rstd * w[c] + b[c];
        __nv_bfloat16 h, l;
        split_bf16(y, h, l);
        ohi[rb + c] = h;
        olo[rb + c] = l;
    }
}

// ---------------------------------------------------------------------------
// Flash attention on mma.sync (bf16x3 for both QK^T and PV; fp32 softmax).
// Grid (T/64, H, B), 128 threads (4 warps x 16 query rows).
// Q,K in [B*T, C] hi/lo; V transposed [B,H,64,T] hi/lo.
// smem: sQ(hi,lo) + 2 stages x (Khi,Klo,Vthi,Vtlo), 144B pitch.
// ---------------------------------------------------------------------------
#define AT_PITCH 144
#define AT_TILE  (64*AT_PITCH)             // 9216
#define AT_STAGE (4*AT_TILE)               // 36864
#define AT_SQ    (2*AT_TILE)               // 18432
#define ATT_SMEM (AT_SQ + 2*AT_STAGE)      // 92160

__global__ __launch_bounds__(128)
void attn_mma_kernel(const __nv_bfloat16* __restrict__ qhi, const __nv_bfloat16* __restrict__ qlo,
                     const __nv_bfloat16* __restrict__ khi, const __nv_bfloat16* __restrict__ klo,
                     const __nv_bfloat16* __restrict__ vthi, const __nv_bfloat16* __restrict__ vtlo,
                     __nv_bfloat16* __restrict__ ohi, __nv_bfloat16* __restrict__ olo)
{
    extern __shared__ char smem[];
    const uint32_t sb = smem_to_u32(smem);
    const int qt = blockIdx.x, h = blockIdx.y, b = blockIdx.z;
    const int t0 = qt * 64;
    const int tid = threadIdx.x, lane = tid & 31, w = tid >> 5;
    const int NCH = qt + 1;                       // 64-key chunks (causal)

    // ---- Q tile load (group 0) ----
    #pragma unroll
    for (int i = 0; i < 8; i++) {
        int c = tid + 128 * i;
        int mat = c >> 9, rem = c & 511, row = rem >> 3, seg = rem & 7;
        const __nv_bfloat16* src = (mat ? qlo : qhi)
            + ((size_t)(b * TT + t0 + row)) * CC + h * 64 + seg * 8;
        CP_ASYNC16(sb + (uint32_t)(mat * AT_TILE + row * AT_PITCH + seg * 16), src, 16);
    }
    CP_COMMIT();

    // ---- K/V chunk loader ----
    auto load_chunk = [&](int cidx) {
        uint32_t st = sb + AT_SQ + (uint32_t)((cidx & 1) * AT_STAGE);
        int j0 = cidx * 64;
        #pragma unroll
        for (int i = 0; i < 16; i++) {
            int c = tid + 128 * i;
            int mat = c >> 9, rem = c & 511, row = rem >> 3, seg = rem & 7;
            const __nv_bfloat16* src;
            if (mat < 2)
                src = (mat ? klo : khi) + ((size_t)(b * TT + j0 + row)) * CC + h * 64 + seg * 8;
            else
                src = ((mat == 2) ? vthi : vtlo)
                    + ((size_t)((b * HH + h) * 64 + row)) * TT + j0 + seg * 8;
            CP_ASYNC16(st + (uint32_t)(mat * AT_TILE + row * AT_PITCH + seg * 16), src, 16);
        }
        CP_COMMIT();
    };

    load_chunk(0);                      // group 1
    if (NCH > 1) load_chunk(1);         // group 2

    // wait for Q, build Q fragments (register-resident for whole kernel)
    if (NCH > 1) { CP_WAIT(2); } else { CP_WAIT(1); }
    __syncthreads();
    const int qrow0 = w * 16;
    uint32_t qh_[4][4], ql_[4][4];
    {
        uint32_t abase = sb + (uint32_t)((qrow0 + (lane & 15)) * AT_PITCH) + (uint32_t)((lane >> 4) * 16);
        #pragma unroll
        for (int kb = 0; kb < 4; kb++) {
            uint32_t ad = abase + (uint32_t)(kb * 32);
            LDSM4(qh_[kb], ad);
            LDSM4(ql_[kb], ad + AT_TILE);
        }
    }

    // softmax state (rows r = qrow0 + lane>>2 and +8)
    float mrow[2] = {-1e30f, -1e30f};
    float lrow[2] = {0.f, 0.f};
    float y[8][4];
    #pragma unroll
    for (int dt = 0; dt < 8; dt++)
        #pragma unroll
        for (int i = 0; i < 4; i++) y[dt][i] = 0.f;

    const uint32_t bRowOff = (uint32_t)(((lane >> 4) * 8 + (lane & 7)) * AT_PITCH);
    const uint32_t bKoff   = (uint32_t)(((lane >> 3) & 1) * 16);

    #pragma unroll 1
    for (int cidx = 0; cidx < NCH; cidx++) {
        if (cidx + 1 < NCH) { CP_WAIT(1); } else { CP_WAIT(0); }
        __syncthreads();
        const uint32_t st = sb + AT_SQ + (uint32_t)((cidx & 1) * AT_STAGE);

        // ---- scores S = Q K^T (bf16x3) ----
        float sc[8][4];
        #pragma unroll
        for (int nt = 0; nt < 8; nt++)
            #pragma unroll
            for (int i = 0; i < 4; i++) sc[nt][i] = 0.f;

        #pragma unroll
        for (int kb = 0; kb < 4; kb++) {
            #pragma unroll
            for (int g = 0; g < 4; g++) {
                uint32_t bd = st + (uint32_t)(g * 16 * AT_PITCH) + bRowOff + (uint32_t)(kb * 32) + bKoff;
                uint32_t bh[4], bl[4];
                LDSM4(bh, bd);
                LDSM4(bl, bd + AT_TILE);
                #pragma unroll
                for (int sub = 0; sub < 2; sub++) {
                    int nt = 2 * g + sub;
                    MMA16816(sc[nt], qh_[kb], &bh[sub * 2]);
                    MMA16816(sc[nt], qh_[kb], &bl[sub * 2]);
                    MMA16816(sc[nt], ql_[kb], &bh[sub * 2]);
                }
            }
        }

        // ---- scale + causal mask + row max ----
        const int j0 = cidx * 64;
        const bool diag = (j0 == t0);
        float rmax[2] = {-1e30f, -1e30f};
        #pragma unroll
        for (int nt = 0; nt < 8; nt++) {
            #pragma unroll
            for (int i = 0; i < 4; i++) {
                float v = sc[nt][i] * 0.125f;
                if (diag) {
                    int colg = j0 + nt * 8 + 2 * (lane & 3) + (i & 1);
                    int rowg = t0 + qrow0 + (lane >> 2) + ((i >> 1) * 8);
                    if (colg > rowg) v = -1e30f;
                }
                sc[nt][i] = v;
                rmax[i >> 1] = fmaxf(rmax[i >> 1], v);
            }
        }
        #pragma unroll
        for (int off = 1; off <= 2; off <<= 1) {
            rmax[0] = fmaxf(rmax[0], __shfl_xor_sync(0xffffffffu, rmax[0], off));
            rmax[1] = fmaxf(rmax[1], __shfl_xor_sync(0xffffffffu, rmax[1], off));
        }

        float newm0 = fmaxf(mrow[0], rmax[0]);
        float newm1 = fmaxf(mrow[1], rmax[1]);
        float alpha0 = fast_exp(mrow[0] - newm0);
        float alpha1 = fast_exp(mrow[1] - newm1);
        mrow[0] = newm0; mrow[1] = newm1;

        // ---- P = exp(S - m), row sums ----
        float psum[2] = {0.f, 0.f};
        #pragma unroll
        for (int nt = 0; nt < 8; nt++) {
            #pragma unroll
            for (int i = 0; i < 4; i++) {
                float p = fast_exp(sc[nt][i] - mrow[i >> 1]);
                sc[nt][i] = p;
                psum[i >> 1] += p;
            }
        }
        #pragma unroll
        for (int off = 1; off <= 2; off <<= 1) {
            psum[0] += __shfl_xor_sync(0xffffffffu, psum[0], off);
            psum[1] += __shfl_xor_sync(0xffffffffu, psum[1], off);
        }
        lrow[0] = lrow[0] * alpha0 + psum[0];
        lrow[1] = lrow[1] * alpha1 + psum[1];

        // rescale y
        #pragma unroll
        for (int dt = 0; dt < 8; dt++) {
            y[dt][0] *= alpha0; y[dt][1] *= alpha0;
            y[dt][2] *= alpha1; y[dt][3] *= alpha1;
        }

        // ---- pack P into A fragments (hi/lo) ----
        uint32_t ph[4][4], pl[4][4];
        #pragma unroll
        for (int jb = 0; jb < 4; jb++) {
            ph[jb][0] = pack_split(sc[2*jb][0],   sc[2*jb][1],   pl[jb][0]);
            ph[jb][1] = pack_split(sc[2*jb][2],   sc[2*jb][3],   pl[jb][1]);
            ph[jb][2] = pack_split(sc[2*jb+1][0], sc[2*jb+1][1], pl[jb][2]);
            ph[jb][3] = pack_split(sc[2*jb+1][2], sc[2*jb+1][3], pl[jb][3]);
        }

        // ---- y += P V (bf16x3), B operand from transposed V ----
        const uint32_t vbase = st + (uint32_t)(2 * AT_TILE);
        #pragma unroll
        for (int jb = 0; jb < 4; jb++) {
            #pragma unroll
            for (int g = 0; g < 4; g++) {
                uint32_t vd = vbase + (uint32_t)(g * 16 * AT_PITCH) + bRowOff + (uint32_t)(jb * 32) + bKoff;
                uint32_t vh[4], vl[4];
                LDSM4(vh, vd);
                LDSM4(vl, vd + AT_TILE);
                #pragma unroll
                for (int sub = 0; sub < 2; sub++) {
                    int dt = 2 * g + sub;
                    MMA16816(y[dt], ph[jb], &vh[sub * 2]);
                    MMA16816(y[dt], ph[jb], &vl[sub * 2]);
                    MMA16816(y[dt], pl[jb], &vh[sub * 2]);
                }
            }
        }
        __syncthreads();

        if (cidx + 2 < NCH) load_chunk(cidx + 2);
    }

    // ---- finalize: y /= l, store hi/lo bf16 ----
    float inv0 = 1.f / lrow[0];
    float inv1 = 1.f / lrow[1];
    int row0 = t0 + qrow0 + (lane >> 2);
    size_t rb0 = ((size_t)(b * TT + row0)) * CC + h * 64;
    size_t rb1 = rb0 + 8 * CC;
    #pragma unroll
    for (int dt = 0; dt < 8; dt++) {
        int col = dt * 8 + 2 * (lane & 3);
        uint32_t lv0, hv0 = pack_split(y[dt][0] * inv0, y[dt][1] * inv0, lv0);
        uint32_t lv1, hv1 = pack_split(y[dt][2] * inv1, y[dt][3] * inv1, lv1);
        *(uint32_t*)(ohi + rb0 + col) = hv0;
        *(uint32_t*)(olo + rb0 + col) = lv0;
        *(uint32_t*)(ohi + rb1 + col) = hv1;
        *(uint32_t*)(olo + rb1 + col) = lv1;
    }
}

// ---------------------------------------------------------------------------
// Loss
// ---------------------------------------------------------------------------
__global__ void loss_row_kernel(const float* __restrict__ logits,
                                const int* __restrict__ tgt,
                                float* __restrict__ nll)
{
    int row = blockIdx.x;
    const float* lr = logits + (size_t)row * VV;
    int tid = threadIdx.x;
    __shared__ float sh[8];
    __shared__ float s_mx;

    float mx = -1e30f;
    for (int i = tid; i < VV; i += 256) mx = fmaxf(mx, lr[i]);
    for (int off = 16; off; off >>= 1)
        mx = fmaxf(mx, __shfl_xor_sync(0xffffffffu, mx, off));
    if ((tid & 31) == 0) sh[tid >> 5] = mx;
    __syncthreads();
    if (tid == 0) {
        float v = sh[0];
        for (int i = 1; i < 8; i++) v = fmaxf(v, sh[i]);
        s_mx = v;
    }
    __syncthreads();
    mx = s_mx;
    __syncthreads();

    float se = 0.f;
    for (int i = tid; i < VV; i += 256) se += fast_exp(lr[i] - mx);
    for (int off = 16; off; off >>= 1)
        se += __shfl_xor_sync(0xffffffffu, se, off);
    if ((tid & 31) == 0) sh[tid >> 5] = se;
    __syncthreads();
    if (tid == 0) {
        float t = 0.f;
        for (int i = 0; i < 8; i++) t += sh[i];
        nll[row] = -(lr[tgt[row]] - mx - logf(t));
    }
}

__global__ void loss_final_kernel(const float* __restrict__ nll,
                                  float* __restrict__ out)
{
    __shared__ float sh[8];
    int tid = threadIdx.x;
    float s = 0.f;
    for (int i = tid; i < MM; i += 256) s += nll[i];
    for (int off = 16; off; off >>= 1)
        s += __shfl_xor_sync(0xffffffffu, s, off);
    if ((tid & 31) == 0) sh[tid >> 5] = s;
    __syncthreads();
    if (tid == 0) {
        float t = 0.f;
        for (int i = 0; i < 8; i++) t += sh[i];
        out[0] = t / (float)MM;
    }
}

// ---------------------------------------------------------------------------
// Host launcher (graph-capturable)
// ---------------------------------------------------------------------------
extern "C" void kernel_launch(void* const* d_in, const int* in_sizes, int n_in,
                              void* d_out, int out_size)
{
    const int*   idx     = (const int*)  d_in[0];
    const int*   targets = (const int*)  d_in[1];
    const float* tok_emb = (const float*)d_in[2];
    const float* pos_emb = (const float*)d_in[3];
    const float* ln1_w   = (const float*)d_in[4];
    const float* ln1_b   = (const float*)d_in[5];
    const float* ln2_w   = (const float*)d_in[6];
    const float* ln2_b   = (const float*)d_in[7];
    const float* Wq      = (const float*)d_in[8];
    const float* bq      = (const float*)d_in[9];
    const float* Wk      = (const float*)d_in[10];
    const float* bk      = (const float*)d_in[11];
    const float* Wv      = (const float*)d_in[12];
    const float* bv      = (const float*)d_in[13];
    const float* Wo      = (const float*)d_in[14];
    const float* bo      = (const float*)d_in[15];
    const float* W1      = (const float*)d_in[16];
    const float* b1      = (const float*)d_in[17];
    const float* W2      = (const float*)d_in[18];
    const float* b2      = (const float*)d_in[19];
    const float* lnf_w   = (const float*)d_in[20];
    const float* lnf_b   = (const float*)d_in[21];
    const float* head_w  = (const float*)d_in[22];
    float* out = (float*)d_out;

    void* p;
    cudaGetSymbolAddress(&p, g_x);   float* x   = (float*)p;
    cudaGetSymbolAddress(&p, g_nll); float* nll = (float*)p;

    __nv_bfloat16 *h_hi, *h_lo, *q_hi, *q_lo, *k_hi, *k_lo, *vt_hi, *vt_lo;
    __nv_bfloat16 *att_hi, *att_lo, *ffn_hi, *ffn_lo;
    cudaGetSymbolAddress(&p, g_h_hi);   h_hi   = (__nv_bfloat16*)p;
    cudaGetSymbolAddress(&p, g_h_lo);   h_lo   = (__nv_bfloat16*)p;
    cudaGetSymbolAddress(&p, g_q_hi);   q_hi   = (__nv_bfloat16*)p;
    cudaGetSymbolAddress(&p, g_q_lo);   q_lo   = (__nv_bfloat16*)p;
    cudaGetSymbolAddress(&p, g_k_hi);   k_hi   = (__nv_bfloat16*)p;
    cudaGetSymbolAddress(&p, g_k_lo);   k_lo   = (__nv_bfloat16*)p;
    cudaGetSymbolAddress(&p, g_vt_hi);  vt_hi  = (__nv_bfloat16*)p;
    cudaGetSymbolAddress(&p, g_vt_lo);  vt_lo  = (__nv_bfloat16*)p;
    cudaGetSymbolAddress(&p, g_att_hi); att_hi = (__nv_bfloat16*)p;
    cudaGetSymbolAddress(&p, g_att_lo); att_lo = (__nv_bfloat16*)p;
    cudaGetSymbolAddress(&p, g_ffn_hi); ffn_hi = (__nv_bfloat16*)p;
    cudaGetSymbolAddress(&p, g_ffn_lo); ffn_lo = (__nv_bfloat16*)p;

    __nv_bfloat16 *wq_hi, *wq_lo, *wk_hi, *wk_lo, *wv_hi, *wv_lo, *wo_hi, *wo_lo;
    __nv_bfloat16 *w1_hi, *w1_lo, *w2_hi, *w2_lo, *wh_hi, *wh_lo;
    cudaGetSymbolAddress(&p, g_wq_hi); wq_hi = (__nv_bfloat16*)p;
    cudaGetSymbolAddress(&p, g_wq_lo); wq_lo = (__nv_bfloat16*)p;
    cudaGetSymbolAddress(&p, g_wk_hi); wk_hi = (__nv_bfloat16*)p;
    cudaGetSymbolAddress(&p, g_wk_lo); wk_lo = (__nv_bfloat16*)p;
    cudaGetSymbolAddress(&p, g_wv_hi); wv_hi = (__nv_bfloat16*)p;
    cudaGetSymbolAddress(&p, g_wv_lo); wv_lo = (__nv_bfloat16*)p;
    cudaGetSymbolAddress(&p, g_wo_hi); wo_hi = (__nv_bfloat16*)p;
    cudaGetSymbolAddress(&p, g_wo_lo); wo_lo = (__nv_bfloat16*)p;
    cudaGetSymbolAddress(&p, g_w1_hi); w1_hi = (__nv_bfloat16*)p;
    cudaGetSymbolAddress(&p, g_w1_lo); w1_lo = (__nv_bfloat16*)p;
    cudaGetSymbolAddress(&p, g_w2_hi); w2_hi = (__nv_bfloat16*)p;
    cudaGetSymbolAddress(&p, g_w2_lo); w2_lo = (__nv_bfloat16*)p;
    cudaGetSymbolAddress(&p, g_wh_hi); wh_hi = (__nv_bfloat16*)p;
    cudaGetSymbolAddress(&p, g_wh_lo); wh_lo = (__nv_bfloat16*)p;

    cudaFuncSetAttribute(gemm_mma_kernel<true,  false, false, true,  false>,
                         cudaFuncAttributeMaxDynamicSharedMemorySize, GEMM_SMEM);
    cudaFuncSetAttribute(gemm_mma_kernel<true,  false, false, false, true>,
                         cudaFuncAttributeMaxDynamicSharedMemorySize, GEMM_SMEM);
    cudaFuncSetAttribute(gemm_mma_kernel<true,  true,  false, false, false>,
                         cudaFuncAttributeMaxDynamicSharedMemorySize, GEMM_SMEM);
    cudaFuncSetAttribute(gemm_mma_kernel<true,  false, true,  true,  false>,
                         cudaFuncAttributeMaxDynamicSharedMemorySize, GEMM_SMEM);
    cudaFuncSetAttribute(gemm_mma_kernel<false, false, false, false, false>,
                         cudaFuncAttributeMaxDynamicSharedMemorySize, GEMM_SMEM);
    cudaFuncSetAttribute(attn_mma_kernel,
                         cudaFuncAttributeMaxDynamicSharedMemorySize, ATT_SMEM);

    // Weight conversion (transpose + bf16 hi/lo split)
    dim3 cb(32, 8);
    convw_kernel<<<dim3(CC / 32, CC / 32, LL), cb>>>(Wq, wq_hi, wq_lo, CC, CC);
    convw_kernel<<<dim3(CC / 32, CC / 32, LL), cb>>>(Wk, wk_hi, wk_lo, CC, CC);
    convw_kernel<<<dim3(CC / 32, CC / 32, LL), cb>>>(Wv, wv_hi, wv_lo, CC, CC);
    convw_kernel<<<dim3(CC / 32, CC / 32, LL), cb>>>(Wo, wo_hi, wo_lo, CC, CC);
    convw_kernel<<<dim3(FF / 32, CC / 32, LL), cb>>>(W1, w1_hi, w1_lo, CC, FF);
    convw_kernel<<<dim3(CC / 32, FF / 32, LL), cb>>>(W2, w2_hi, w2_lo, FF, CC);
    convw_kernel<<<dim3((VV + 31) / 32, CC / 32, 1), cb>>>(head_w, wh_hi, wh_lo, CC, VV);

    dim3 gCC(MM / 128, CC / 128);
    dim3 gCF(MM / 128, FF / 128);
    dim3 gCV(MM / 128, (VV + 127) / 128);

    embed_kernel<<<MM, 256>>>(idx, tok_emb, pos_emb, x);

    for (int l = 0; l < LL; l++) {
        size_t oCC = (size_t)l * CC * CC;
        size_t oCF = (size_t)l * CC * FF;

        ln_kernel<<<MM, 256>>>(x, ln1_w + (size_t)l * CC, ln1_b + (size_t)l * CC, h_hi, h_lo);
        gemm_mma_kernel<true, false, false, true, false><<<gCC, 256, GEMM_SMEM>>>(
            h_hi, h_lo, wq_hi + oCC, wq_lo + oCC, bq + (size_t)l * CC,
            nullptr, nullptr, q_hi, q_lo, MM, CC, CC);
        gemm_mma_kernel<true, false, false, true, false><<<gCC, 256, GEMM_SMEM>>>(
            h_hi, h_lo, wk_hi + oCC, wk_lo + oCC, bk + (size_t)l * CC,
            nullptr, nullptr, k_hi, k_lo, MM, CC, CC);
        gemm_mma_kernel<true, false, false, false, true><<<gCC, 256, GEMM_SMEM>>>(
            h_hi, h_lo, wv_hi + oCC, wv_lo + oCC, bv + (size_t)l * CC,
            nullptr, nullptr, vt_hi, vt_lo, MM, CC, CC);
        attn_mma_kernel<<<dim3(TT / 64, HH, BB), 128, ATT_SMEM>>>(
            q_hi, q_lo, k_hi, k_lo, vt_hi, vt_lo, att_hi, att_lo);
        gemm_mma_kernel<true, true, false, false, false><<<gCC, 256, GEMM_SMEM>>>(
            att_hi, att_lo, wo_hi + oCC, wo_lo + oCC, bo + (size_t)l * CC,
            x, x, nullptr, nullptr, MM, CC, CC);
        ln_kernel<<<MM, 256>>>(x, ln2_w + (size_t)l * CC, ln2_b + (size_t)l * CC, h_hi, h_lo);
        gemm_mma_kernel<true, false, true, true, false><<<gCF, 256, GEMM_SMEM>>>(
            h_hi, h_lo, w1_hi + oCF, w1_lo + oCF, b1 + (size_t)l * FF,
            nullptr, nullptr, ffn_hi, ffn_lo, MM, FF, CC);
        gemm_mma_kernel<true, true, false, false, false><<<gCC, 256, GEMM_SMEM>>>(
            ffn_hi, ffn_lo, w2_hi + oCF, w2_lo + oCF, b2 + (size_t)l * CC,
            x, x, nullptr, nullptr, MM, CC, FF);
    }

    ln_kernel<<<MM, 256>>>(x, lnf_w, lnf_b, h_hi, h_lo);
    gemm_mma_kernel<false, false, false, false, false><<<gCV, 256, GEMM_SMEM>>>(
        h_hi, h_lo, wh_hi, wh_lo, nullptr, nullptr, out, nullptr, nullptr, MM, VV, CC);

    loss_row_kernel<<<MM, 256>>>(out, targets, nll);
    size_t NL = (size_t)MM * VV;
    if ((size_t)out_size > NL)
        loss_final_kernel<<<1, 256>>>(nll, out + NL);
}